// round 15
// baseline (speedup 1.0000x reference)
#include <cuda_runtime.h>
#include <cuda_bf16.h>
#include <math.h>
#include <stdint.h>

#define MAXN 200704

// ---------------- scratch (static device globals; no runtime allocation) ----
__device__ __nv_bfloat16 g_h_hi[(size_t)MAXN * 256];
__device__ __nv_bfloat16 g_h_lo[(size_t)MAXN * 256];
__device__ __nv_bfloat16 g_W1T_hi[256 * 512];
__device__ __nv_bfloat16 g_W1T_lo[256 * 512];
__device__ __nv_bfloat16 g_WabT_hi[512 * 256];   // col-interleaved [Wa|Wb], [n][k]
__device__ __nv_bfloat16 g_WabT_lo[512 * 256];
__device__ float d_raw[MAXN];
__device__ float d_pm[256];
__device__ float d_ps[256];
__device__ float d_stats[2];
__device__ float d_pgf[256 * 256];

// ---------------- helpers ----------------
__device__ __forceinline__ uint32_t smem_u32(const void* p) {
    uint32_t a;
    asm("{ .reg .u64 t; cvta.to.shared.u64 t, %1; cvt.u32.u64 %0, t; }" : "=r"(a) : "l"(p));
    return a;
}
__device__ __forceinline__ void cp16(uint32_t dst, const void* src) {
    asm volatile("cp.async.cg.shared.global [%0], [%1], 16;" :: "r"(dst), "l"(src));
}
#define CP_COMMIT() asm volatile("cp.async.commit_group;" ::: "memory")
#define CP_WAIT0()  asm volatile("cp.async.wait_group 0;" ::: "memory")
#define CP_WAIT1()  asm volatile("cp.async.wait_group 1;" ::: "memory")

#define LDSM4(r, addr) \
    asm volatile("ldmatrix.sync.aligned.m8n8.x4.shared.b16 {%0,%1,%2,%3}, [%4];" \
        : "=r"((r)[0]), "=r"((r)[1]), "=r"((r)[2]), "=r"((r)[3]) : "r"(addr))

__device__ __forceinline__ void mma16816(float* c, const uint32_t* a, uint32_t b0, uint32_t b1) {
    asm volatile("mma.sync.aligned.m16n8k16.row.col.f32.bf16.bf16.f32 "
        "{%0,%1,%2,%3}, {%4,%5,%6,%7}, {%8,%9}, {%0,%1,%2,%3};"
        : "+f"(c[0]), "+f"(c[1]), "+f"(c[2]), "+f"(c[3])
        : "r"(a[0]), "r"(a[1]), "r"(a[2]), "r"(a[3]), "r"(b0), "r"(b1));
}

__device__ __forceinline__ void splitpair(float v0, float v1, uint32_t& hi, uint32_t& lo) {
    __nv_bfloat162 h = __floats2bfloat162_rn(v0, v1);
    float l0 = v0 - __bfloat162float(h.x);
    float l1 = v1 - __bfloat162float(h.y);
    __nv_bfloat162 l = __floats2bfloat162_rn(l0, l1);
    hi = *reinterpret_cast<uint32_t*>(&h);
    lo = *reinterpret_cast<uint32_t*>(&l);
}

// ---------------- prep: transpose+split weights to bf16 hi/lo ----------------
__global__ __launch_bounds__(256) void prep_w1(const float* __restrict__ W1)
{
    int o = blockIdx.x * 256 + threadIdx.x;   // 512 blocks -> 131072
    int n = o >> 9, k = o & 511;
    float v = W1[k * 256 + n];
    __nv_bfloat16 h = __float2bfloat16(v);
    g_W1T_hi[o] = h;
    g_W1T_lo[o] = __float2bfloat16(v - __bfloat162float(h));
}
__global__ __launch_bounds__(256) void prep_wab(
    const float* __restrict__ Wa, const float* __restrict__ Wb)
{
    int o = blockIdx.x * 256 + threadIdx.x;   // 512 blocks -> 131072
    int n = o >> 8, k = o & 255;
    int j = n >> 1;
    float v = (n & 1) ? Wb[k * 256 + j] : Wa[k * 256 + j];
    __nv_bfloat16 h = __float2bfloat16(v);
    g_WabT_hi[o] = h;
    g_WabT_lo[o] = __float2bfloat16(v - __bfloat162float(h));
}

// ---------------- GEMM1: h = relu(x@W1+b1) -----------------------------------
// CTA tile 128x256 (full N, both n-halves accumulator-resident), BK=32,
// 8 warps (2m x 4n), warp covers 64x32 in each n-half. 3-stage cp.async.
// Inner MMA issue is TERM-MAJOR: 16 independent accumulators between RAW reuse.
#define P1 40
#define S1_AL 10240
#define S1_BH 20480
#define S1_BL 40960
#define STG1  61440
#define SMEM1 (3 * STG1)

__global__ __launch_bounds__(256, 1) void gemm1_kernel(
    const float* __restrict__ Xf, const float* __restrict__ bias1, int M)
{
    extern __shared__ char dsm[];
    const uint32_t sb = smem_u32(dsm);
    const int t = threadIdx.x;
    const int lane = t & 31, w = t >> 5;
    const int m0 = blockIdx.x * 128;
    const int wm = (w >> 2) * 64, wn = (w & 3) * 32;

    float areg[16];
    const int arow = t >> 1, akh = t & 1;

    auto loadB = [&](int stg, int kt) {
        uint32_t dBh = sb + stg * STG1 + S1_BH;
        uint32_t dBl = sb + stg * STG1 + S1_BL;
        #pragma unroll
        for (int i = 0; i < 4; i++) {
            int id = t + 256 * i;
            int row = id >> 2, kc = (id & 3) * 8;
            uint32_t doff = (uint32_t)(row * P1 + kc) * 2;
            size_t so = (size_t)row * 512 + kt + kc;
            cp16(dBh + doff, g_W1T_hi + so);
            cp16(dBl + doff, g_W1T_lo + so);
        }
    };
    auto ldgA = [&](int kt) {
        const float* src = Xf + (size_t)(m0 + arow) * 512 + kt + akh * 16;
        bool ok = (m0 + arow) < M;
        #pragma unroll
        for (int q = 0; q < 4; q++) {
            float4 v = ok ? *(const float4*)(src + q * 4) : make_float4(0.f, 0.f, 0.f, 0.f);
            areg[q * 4 + 0] = v.x; areg[q * 4 + 1] = v.y;
            areg[q * 4 + 2] = v.z; areg[q * 4 + 3] = v.w;
        }
    };
    auto stsA = [&](int stg) {
        uint32_t hi[8], lo[8];
        #pragma unroll
        for (int p = 0; p < 8; p++) splitpair(areg[2 * p], areg[2 * p + 1], hi[p], lo[p]);
        char* bh = dsm + stg * STG1 + (arow * P1 + akh * 16) * 2;
        char* bl = bh + S1_AL;
        *(uint4*)(bh)      = make_uint4(hi[0], hi[1], hi[2], hi[3]);
        *(uint4*)(bh + 16) = make_uint4(hi[4], hi[5], hi[6], hi[7]);
        *(uint4*)(bl)      = make_uint4(lo[0], lo[1], lo[2], lo[3]);
        *(uint4*)(bl + 16) = make_uint4(lo[4], lo[5], lo[6], lo[7]);
    };

    float acc[2][4][4][4];
    #pragma unroll
    for (int hf = 0; hf < 2; hf++)
        #pragma unroll
        for (int mi = 0; mi < 4; mi++)
            #pragma unroll
            for (int ni = 0; ni < 4; ni++)
                #pragma unroll
                for (int q = 0; q < 4; q++) acc[hf][mi][ni][q] = 0.f;

    ldgA(0);  stsA(0); loadB(0, 0);  CP_COMMIT();
    ldgA(32); stsA(1); loadB(1, 32); CP_COMMIT();

    const int S_ = 16;
    for (int s = 0; s < S_; s++) {
        int stg = s % 3;
        if (s < S_ - 1) CP_WAIT1(); else CP_WAIT0();
        __syncthreads();
        bool pf = (s + 2 < S_);
        if (pf) { ldgA((s + 2) * 32); loadB((s + 2) % 3, (s + 2) * 32); CP_COMMIT(); }

        uint32_t base = sb + stg * STG1;
        #pragma unroll
        for (int kk = 0; kk < 32; kk += 16) {
            uint32_t ah[4][4], al[4][4];
            #pragma unroll
            for (int mi = 0; mi < 4; mi++) {
                int row = wm + mi * 16 + (lane & 15);
                int col = kk + 8 * (lane >> 4);
                uint32_t off = (uint32_t)(row * P1 + col) * 2;
                LDSM4(ah[mi], base + off);
                LDSM4(al[mi], base + S1_AL + off);
            }
            #pragma unroll
            for (int hf = 0; hf < 2; hf++) {
                uint32_t bh[2][4], bl[2][4];
                #pragma unroll
                for (int nj = 0; nj < 2; nj++) {
                    int rown = hf * 128 + wn + nj * 16 + (lane & 7) + 8 * (lane >> 4);
                    int coln = kk + 8 * ((lane >> 3) & 1);
                    uint32_t off = (uint32_t)(rown * P1 + coln) * 2;
                    LDSM4(bh[nj], base + S1_BH + off);
                    LDSM4(bl[nj], base + S1_BL + off);
                }
                // term-major sweeps: 16 independent accumulators per sweep
                #pragma unroll
                for (int mi = 0; mi < 4; mi++)
                    #pragma unroll
                    for (int ni = 0; ni < 4; ni++)
                        mma16816(acc[hf][mi][ni], ah[mi],
                                 bh[ni >> 1][(ni & 1) * 2], bh[ni >> 1][(ni & 1) * 2 + 1]);
                #pragma unroll
                for (int mi = 0; mi < 4; mi++)
                    #pragma unroll
                    for (int ni = 0; ni < 4; ni++)
                        mma16816(acc[hf][mi][ni], ah[mi],
                                 bl[ni >> 1][(ni & 1) * 2], bl[ni >> 1][(ni & 1) * 2 + 1]);
                #pragma unroll
                for (int mi = 0; mi < 4; mi++)
                    #pragma unroll
                    for (int ni = 0; ni < 4; ni++)
                        mma16816(acc[hf][mi][ni], al[mi],
                                 bh[ni >> 1][(ni & 1) * 2], bh[ni >> 1][(ni & 1) * 2 + 1]);
            }
        }
        if (pf) stsA((s + 2) % 3);
    }

    // epilogue: bias + relu + split-store h hi/lo (full 256 cols)
    #pragma unroll
    for (int hf = 0; hf < 2; hf++)
        #pragma unroll
        for (int mi = 0; mi < 4; mi++) {
            #pragma unroll
            for (int h = 0; h < 2; h++) {
                int r = m0 + wm + mi * 16 + (lane >> 2) + 8 * h;
                if (r < M) {
                    #pragma unroll
                    for (int ni = 0; ni < 4; ni++) {
                        int col = hf * 128 + wn + ni * 8 + (lane & 3) * 2;
                        float v0 = fmaxf(acc[hf][mi][ni][2 * h + 0] + __ldg(bias1 + col), 0.f);
                        float v1 = fmaxf(acc[hf][mi][ni][2 * h + 1] + __ldg(bias1 + col + 1), 0.f);
                        uint32_t hi, lo;
                        splitpair(v0, v1, hi, lo);
                        *(uint32_t*)(g_h_hi + (size_t)r * 256 + col) = hi;
                        *(uint32_t*)(g_h_lo + (size_t)r * 256 + col) = lo;
                    }
                }
            }
        }
}

// ------- GEMM2: A-resident h tile; 2 n-blocks accumulator-resident per pass --
// 2 passes x 8 k-chunks. B double-buffered. Term-major MMA issue.
#define A2_PITCH 264
#define A2_BYTES (128 * A2_PITCH * 2)      // 67584 per array
#define B2_OFF   (2 * A2_BYTES)            // 135168
#define B2_BUF   40960                     // Bh(20480)+Bl(20480)
#define SMEM2    (B2_OFF + 2 * B2_BUF)     // 217088

__global__ __launch_bounds__(256, 1) void gemm2_kernel(
    const float* __restrict__ ba, const float* __restrict__ bb,
    const float* __restrict__ Wc, int M)
{
    extern __shared__ char dsm[];
    const uint32_t sb = smem_u32(dsm);
    __shared__ float sba[256], sbb[256], sWc[256], spart[512];
    const int t = threadIdx.x;
    const int lane = t & 31, w = t >> 5;
    const int m0 = blockIdx.x * 128;
    const int wm = (w >> 2) * 64, wn = (w & 3) * 32;

    sba[t] = ba[t]; sbb[t] = bb[t]; sWc[t] = Wc[t];

    auto loadB = [&](int buf, int u) {
        int pass = u >> 3, kc = u & 7;
        uint32_t dBh = sb + B2_OFF + buf * B2_BUF;
        uint32_t dBl = dBh + 20480;
        #pragma unroll
        for (int i = 0; i < 4; i++) {
            int id = t + 256 * i;
            int row = id >> 2, kcol = (id & 3) * 8;
            int nglob = (pass * 2 + (row >> 7)) * 128 + (row & 127);
            uint32_t doff = (uint32_t)(row * P1 + kcol) * 2;
            size_t so = (size_t)nglob * 256 + kc * 32 + kcol;
            cp16(dBh + doff, g_WabT_hi + so);
            cp16(dBl + doff, g_WabT_lo + so);
        }
    };

    // load full A tile (h hi/lo, 128 rows x 256 k) into resident SMEM
    #pragma unroll
    for (int i = 0; i < 16; i++) {
        int id = t + 256 * i;
        int row = id >> 5, ch = id & 31;
        uint32_t doff = (uint32_t)(row * A2_PITCH + ch * 8) * 2;
        size_t so = (size_t)(m0 + row) * 256 + ch * 8;
        cp16(sb + doff, g_h_hi + so);
        cp16(sb + A2_BYTES + doff, g_h_lo + so);
    }
    loadB(0, 0);
    CP_COMMIT(); CP_WAIT0();
    __syncthreads();

    float acc[2][4][4][4];
    float rp[4][2];
    #pragma unroll
    for (int mi = 0; mi < 4; mi++) { rp[mi][0] = 0.f; rp[mi][1] = 0.f; }

    for (int pass = 0; pass < 2; pass++) {
        #pragma unroll
        for (int nb = 0; nb < 2; nb++)
            #pragma unroll
            for (int mi = 0; mi < 4; mi++)
                #pragma unroll
                for (int ni = 0; ni < 4; ni++)
                    #pragma unroll
                    for (int q = 0; q < 4; q++) acc[nb][mi][ni][q] = 0.f;

        for (int kc = 0; kc < 8; kc++) {
            int u = pass * 8 + kc;
            int buf = u & 1;
            if (u + 1 < 16) { loadB(buf ^ 1, u + 1); CP_COMMIT(); }

            uint32_t baseB = sb + B2_OFF + buf * B2_BUF;
            #pragma unroll
            for (int kk = 0; kk < 32; kk += 16) {
                uint32_t ah[4][4], al[4][4];
                #pragma unroll
                for (int mi = 0; mi < 4; mi++) {
                    int row = wm + mi * 16 + (lane & 15);
                    int colg = kc * 32 + kk + 8 * (lane >> 4);
                    uint32_t off = (uint32_t)(row * A2_PITCH + colg) * 2;
                    LDSM4(ah[mi], sb + off);
                    LDSM4(al[mi], sb + A2_BYTES + off);
                }
                #pragma unroll
                for (int nb = 0; nb < 2; nb++) {
                    uint32_t bh[2][4], bl[2][4];
                    #pragma unroll
                    for (int nj = 0; nj < 2; nj++) {
                        int rown = nb * 128 + wn + nj * 16 + (lane & 7) + 8 * (lane >> 4);
                        int coln = kk + 8 * ((lane >> 3) & 1);
                        uint32_t off = (uint32_t)(rown * P1 + coln) * 2;
                        LDSM4(bh[nj], baseB + off);
                        LDSM4(bl[nj], baseB + 20480 + off);
                    }
                    // term-major sweeps: 16 independent accumulators per sweep
                    #pragma unroll
                    for (int mi = 0; mi < 4; mi++)
                        #pragma unroll
                        for (int ni = 0; ni < 4; ni++)
                            mma16816(acc[nb][mi][ni], ah[mi],
                                     bh[ni >> 1][(ni & 1) * 2], bh[ni >> 1][(ni & 1) * 2 + 1]);
                    #pragma unroll
                    for (int mi = 0; mi < 4; mi++)
                        #pragma unroll
                        for (int ni = 0; ni < 4; ni++)
                            mma16816(acc[nb][mi][ni], ah[mi],
                                     bl[ni >> 1][(ni & 1) * 2], bl[ni >> 1][(ni & 1) * 2 + 1]);
                    #pragma unroll
                    for (int mi = 0; mi < 4; mi++)
                        #pragma unroll
                        for (int ni = 0; ni < 4; ni++)
                            mma16816(acc[nb][mi][ni], al[mi],
                                     bh[ni >> 1][(ni & 1) * 2], bh[ni >> 1][(ni & 1) * 2 + 1]);
                }
            }
            if (kc == 7) {      // fold both n-blocks of this pass into raw partials
                #pragma unroll
                for (int nb = 0; nb < 2; nb++)
                    #pragma unroll
                    for (int mi = 0; mi < 4; mi++)
                        #pragma unroll
                        for (int ni = 0; ni < 4; ni++) {
                            int j = ((pass * 2 + nb) * 128 + wn + ni * 8 + (lane & 3) * 2) >> 1;
                            float bav = sba[j], bbv = sbb[j], wcv = sWc[j];
                            float av0 = acc[nb][mi][ni][0] + bav;
                            float bv0 = acc[nb][mi][ni][1] + bbv;
                            rp[mi][0] += tanhf(av0) * (1.f / (1.f + expf(-bv0))) * wcv;
                            float av1 = acc[nb][mi][ni][2] + bav;
                            float bv1 = acc[nb][mi][ni][3] + bbv;
                            rp[mi][1] += tanhf(av1) * (1.f / (1.f + expf(-bv1))) * wcv;
                        }
            }
            CP_WAIT0();
            __syncthreads();
        }
    }

    // reduce rp across quads then across the 4 n-warps
    #pragma unroll
    for (int mi = 0; mi < 4; mi++)
        #pragma unroll
        for (int h = 0; h < 2; h++) {
            rp[mi][h] += __shfl_xor_sync(0xffffffffu, rp[mi][h], 1);
            rp[mi][h] += __shfl_xor_sync(0xffffffffu, rp[mi][h], 2);
        }
    if ((lane & 3) == 0) {
        #pragma unroll
        for (int mi = 0; mi < 4; mi++)
            #pragma unroll
            for (int h = 0; h < 2; h++) {
                int rit = wm + mi * 16 + (lane >> 2) + 8 * h;
                spart[rit * 4 + (w & 3)] = rp[mi][h];
            }
    }
    __syncthreads();
    if (t < 128) {
        int r = m0 + t;
        if (r < M)
            d_raw[r] = spart[t * 4] + spart[t * 4 + 1] + spart[t * 4 + 2] + spart[t * 4 + 3];
    }
}

// ---------------- softmax partials over raw (deterministic two-stage) -------
__global__ __launch_bounds__(256) void stats1_kernel(int M)
{
    __shared__ float red[256];
    int t = threadIdx.x, b = blockIdx.x;
    int idx0 = b * 256 + t;
    float m = -INFINITY;
    for (int i = idx0; i < M; i += 65536) m = fmaxf(m, d_raw[i]);
    red[t] = m; __syncthreads();
    #pragma unroll
    for (int o = 128; o; o >>= 1) { if (t < o) red[t] = fmaxf(red[t], red[t + o]); __syncthreads(); }
    float bm = red[0];
    __syncthreads();
    float s = 0.f;
    for (int i = idx0; i < M; i += 65536) s += expf(d_raw[i] - bm);
    red[t] = s; __syncthreads();
    #pragma unroll
    for (int o = 128; o; o >>= 1) { if (t < o) red[t] += red[t + o]; __syncthreads(); }
    if (t == 0) { d_pm[b] = bm; d_ps[b] = red[0]; }
}

__global__ __launch_bounds__(256) void stats2_kernel()
{
    __shared__ float red[256];
    int t = threadIdx.x;
    float m = d_pm[t];
    red[t] = m; __syncthreads();
    #pragma unroll
    for (int o = 128; o; o >>= 1) { if (t < o) red[t] = fmaxf(red[t], red[t + o]); __syncthreads(); }
    float gmax = red[0];
    __syncthreads();
    float s = d_ps[t] * expf(m - gmax);
    red[t] = s; __syncthreads();
    #pragma unroll
    for (int o = 128; o; o >>= 1) { if (t < o) red[t] += red[t + o]; __syncthreads(); }
    if (t == 0) { d_stats[0] = gmax; d_stats[1] = red[0]; }
}

// ---------------- A = softmax(raw) -> out[0..M); partial gf = A@h ------------
__global__ __launch_bounds__(256) void afeat_kernel(float* __restrict__ out, int M)
{
    int t = threadIdx.x, b = blockIdx.x;
    int chunk = (M + 255) >> 8;
    int start = b * chunk;
    int end   = min(start + chunk, M);
    float gmax = d_stats[0];
    float inv  = 1.f / d_stats[1];
    float acc = 0.f;
    for (int r = start; r < end; r++) {
        float ar = expf(d_raw[r] - gmax) * inv;
        if ((r & 255) == t) out[r] = ar;
        size_t idx = (size_t)r * 256 + t;
        float hv = __bfloat162float(g_h_hi[idx]) + __bfloat162float(g_h_lo[idx]);
        acc = fmaf(ar, hv, acc);
    }
    d_pgf[b * 256 + t] = acc;
}

// ---------------- final: gf, hr = relu(gf@Wr+br), cls/reg heads --------------
__global__ __launch_bounds__(256) void head_kernel(
    const float* __restrict__ Wr,   const float* __restrict__ br,
    const float* __restrict__ Wcls, const float* __restrict__ bcls,
    const float* __restrict__ Wreg, const float* __restrict__ breg,
    float* __restrict__ out, int M)
{
    __shared__ float sgf[256], shr[256];
    int t = threadIdx.x;
    float acc = 0.f;
    #pragma unroll 8
    for (int b = 0; b < 256; b++) acc += d_pgf[b * 256 + t];
    sgf[t] = acc;
    out[M + t] = acc;
    __syncthreads();
    float v = br[t];
    #pragma unroll 8
    for (int k = 0; k < 256; k++) v = fmaf(sgf[k], Wr[k * 256 + t], v);
    shr[t] = fmaxf(v, 0.f);
    __syncthreads();
    if (t < 33) {
        float c = bcls[t];
        #pragma unroll 8
        for (int k = 0; k < 256; k++) c = fmaf(shr[k], Wcls[k * 33 + t], c);
        out[M + 256 + t] = c;
    } else if (t >= 64 && t < 119) {
        int j = t - 64;
        float c = breg[j];
        #pragma unroll 8
        for (int k = 0; k < 256; k++) c = fmaf(shr[k], Wreg[k * 55 + j], c);
        out[M + 289 + j] = c;
    }
}

// ---------------- launch ----------------
extern "C" void kernel_launch(void* const* d_in, const int* in_sizes, int n_in,
                              void* d_out, int out_size)
{
    const float* x    = (const float*)d_in[0];
    const float* W1   = (const float*)d_in[1];
    const float* b1   = (const float*)d_in[2];
    const float* Wa   = (const float*)d_in[3];
    const float* ba   = (const float*)d_in[4];
    const float* Wb   = (const float*)d_in[5];
    const float* bb   = (const float*)d_in[6];
    const float* Wc   = (const float*)d_in[7];
    // d_in[8] = bc : constant shift, cancels in softmax -> unused
    const float* Wr   = (const float*)d_in[9];
    const float* br   = (const float*)d_in[10];
    const float* Wcls = (const float*)d_in[11];
    const float* bcls = (const float*)d_in[12];
    const float* Wreg = (const float*)d_in[13];
    const float* breg = (const float*)d_in[14];
    float* out = (float*)d_out;
    int M = in_sizes[0] / 512;

    cudaFuncSetAttribute(gemm1_kernel, cudaFuncAttributeMaxDynamicSharedMemorySize, SMEM1);
    cudaFuncSetAttribute(gemm2_kernel, cudaFuncAttributeMaxDynamicSharedMemorySize, SMEM2);

    prep_w1 <<<512, 256>>>(W1);                                   // launch 1
    prep_wab<<<512, 256>>>(Wa, Wb);                               // launch 2
    gemm1_kernel<<<(M + 127) / 128, 256, SMEM1>>>(x, b1, M);      // launch 3
    gemm2_kernel<<<(M + 127) / 128, 256, SMEM2>>>(ba, bb, Wc, M); // launch 4 (profiled)
    stats1_kernel<<<256, 256>>>(M);
    stats2_kernel<<<1, 256>>>();
    afeat_kernel<<<256, 256>>>(out, M);
    head_kernel<<<1, 256>>>(Wr, br, Wcls, bcls, Wreg, breg, out, M);
}

// round 16
// speedup vs baseline: 1.0033x; 1.0033x over previous
#include <cuda_runtime.h>
#include <cuda_bf16.h>
#include <math.h>
#include <stdint.h>

#define MAXN 200704

// ---------------- scratch (static device globals; no runtime allocation) ----
__device__ __nv_bfloat16 g_h_hi[(size_t)MAXN * 256];
__device__ __nv_bfloat16 g_h_lo[(size_t)MAXN * 256];
__device__ __nv_bfloat16 g_W1T_hi[256 * 512];
__device__ __nv_bfloat16 g_W1T_lo[256 * 512];
__device__ __nv_bfloat16 g_WabT_hi[512 * 256];   // col-interleaved [Wa|Wb], [n][k]
__device__ __nv_bfloat16 g_WabT_lo[512 * 256];
__device__ float d_raw[MAXN];
__device__ float d_pm[256];
__device__ float d_ps[256];
__device__ float d_stats[2];
__device__ float d_pgf[256 * 256];

// ---------------- helpers ----------------
__device__ __forceinline__ uint32_t smem_u32(const void* p) {
    uint32_t a;
    asm("{ .reg .u64 t; cvta.to.shared.u64 t, %1; cvt.u32.u64 %0, t; }" : "=r"(a) : "l"(p));
    return a;
}
__device__ __forceinline__ void cp16(uint32_t dst, const void* src) {
    asm volatile("cp.async.cg.shared.global [%0], [%1], 16;" :: "r"(dst), "l"(src));
}
#define CP_COMMIT() asm volatile("cp.async.commit_group;" ::: "memory")
#define CP_WAIT0()  asm volatile("cp.async.wait_group 0;" ::: "memory")
#define CP_WAIT1()  asm volatile("cp.async.wait_group 1;" ::: "memory")

#define LDSM4(r, addr) \
    asm volatile("ldmatrix.sync.aligned.m8n8.x4.shared.b16 {%0,%1,%2,%3}, [%4];" \
        : "=r"((r)[0]), "=r"((r)[1]), "=r"((r)[2]), "=r"((r)[3]) : "r"(addr))

__device__ __forceinline__ void mma16816(float* c, const uint32_t* a, uint32_t b0, uint32_t b1) {
    asm volatile("mma.sync.aligned.m16n8k16.row.col.f32.bf16.bf16.f32 "
        "{%0,%1,%2,%3}, {%4,%5,%6,%7}, {%8,%9}, {%0,%1,%2,%3};"
        : "+f"(c[0]), "+f"(c[1]), "+f"(c[2]), "+f"(c[3])
        : "r"(a[0]), "r"(a[1]), "r"(a[2]), "r"(a[3]), "r"(b0), "r"(b1));
}

__device__ __forceinline__ void splitpair(float v0, float v1, uint32_t& hi, uint32_t& lo) {
    __nv_bfloat162 h = __floats2bfloat162_rn(v0, v1);
    float l0 = v0 - __bfloat162float(h.x);
    float l1 = v1 - __bfloat162float(h.y);
    __nv_bfloat162 l = __floats2bfloat162_rn(l0, l1);
    hi = *reinterpret_cast<uint32_t*>(&h);
    lo = *reinterpret_cast<uint32_t*>(&l);
}

// ---------------- prep: transpose+split weights to bf16 hi/lo ----------------
__global__ __launch_bounds__(256) void prep_w1(const float* __restrict__ W1)
{
    int o = blockIdx.x * 256 + threadIdx.x;   // 512 blocks -> 131072
    int n = o >> 9, k = o & 511;
    float v = W1[k * 256 + n];
    __nv_bfloat16 h = __float2bfloat16(v);
    g_W1T_hi[o] = h;
    g_W1T_lo[o] = __float2bfloat16(v - __bfloat162float(h));
}
__global__ __launch_bounds__(256) void prep_wab(
    const float* __restrict__ Wa, const float* __restrict__ Wb)
{
    int o = blockIdx.x * 256 + threadIdx.x;   // 512 blocks -> 131072
    int n = o >> 8, k = o & 255;
    int j = n >> 1;
    float v = (n & 1) ? Wb[k * 256 + j] : Wa[k * 256 + j];
    __nv_bfloat16 h = __float2bfloat16(v);
    g_WabT_hi[o] = h;
    g_WabT_lo[o] = __float2bfloat16(v - __bfloat162float(h));
}

// ---------------- GEMM1: h = relu(x@W1+b1) -----------------------------------
// CTA tile 128x256 (full N, both n-halves accumulator-resident), BK=32,
// 8 warps (2m x 4n), warp covers 64x32 in each n-half. 3-stage cp.async.
// Inner MMA issue is TERM-MAJOR: 16 independent accumulators between RAW reuse.
#define P1 40
#define S1_AL 10240
#define S1_BH 20480
#define S1_BL 40960
#define STG1  61440
#define SMEM1 (3 * STG1)

__global__ __launch_bounds__(256, 1) void gemm1_kernel(
    const float* __restrict__ Xf, const float* __restrict__ bias1, int M)
{
    extern __shared__ char dsm[];
    const uint32_t sb = smem_u32(dsm);
    const int t = threadIdx.x;
    const int lane = t & 31, w = t >> 5;
    const int m0 = blockIdx.x * 128;
    const int wm = (w >> 2) * 64, wn = (w & 3) * 32;

    float areg[16];
    const int arow = t >> 1, akh = t & 1;

    auto loadB = [&](int stg, int kt) {
        uint32_t dBh = sb + stg * STG1 + S1_BH;
        uint32_t dBl = sb + stg * STG1 + S1_BL;
        #pragma unroll
        for (int i = 0; i < 4; i++) {
            int id = t + 256 * i;
            int row = id >> 2, kc = (id & 3) * 8;
            uint32_t doff = (uint32_t)(row * P1 + kc) * 2;
            size_t so = (size_t)row * 512 + kt + kc;
            cp16(dBh + doff, g_W1T_hi + so);
            cp16(dBl + doff, g_W1T_lo + so);
        }
    };
    auto ldgA = [&](int kt) {
        const float* src = Xf + (size_t)(m0 + arow) * 512 + kt + akh * 16;
        bool ok = (m0 + arow) < M;
        #pragma unroll
        for (int q = 0; q < 4; q++) {
            float4 v = ok ? *(const float4*)(src + q * 4) : make_float4(0.f, 0.f, 0.f, 0.f);
            areg[q * 4 + 0] = v.x; areg[q * 4 + 1] = v.y;
            areg[q * 4 + 2] = v.z; areg[q * 4 + 3] = v.w;
        }
    };
    auto stsA = [&](int stg) {
        uint32_t hi[8], lo[8];
        #pragma unroll
        for (int p = 0; p < 8; p++) splitpair(areg[2 * p], areg[2 * p + 1], hi[p], lo[p]);
        char* bh = dsm + stg * STG1 + (arow * P1 + akh * 16) * 2;
        char* bl = bh + S1_AL;
        *(uint4*)(bh)      = make_uint4(hi[0], hi[1], hi[2], hi[3]);
        *(uint4*)(bh + 16) = make_uint4(hi[4], hi[5], hi[6], hi[7]);
        *(uint4*)(bl)      = make_uint4(lo[0], lo[1], lo[2], lo[3]);
        *(uint4*)(bl + 16) = make_uint4(lo[4], lo[5], lo[6], lo[7]);
    };

    float acc[2][4][4][4];
    #pragma unroll
    for (int hf = 0; hf < 2; hf++)
        #pragma unroll
        for (int mi = 0; mi < 4; mi++)
            #pragma unroll
            for (int ni = 0; ni < 4; ni++)
                #pragma unroll
                for (int q = 0; q < 4; q++) acc[hf][mi][ni][q] = 0.f;

    ldgA(0);  stsA(0); loadB(0, 0);  CP_COMMIT();
    ldgA(32); stsA(1); loadB(1, 32); CP_COMMIT();

    const int S_ = 16;
    for (int s = 0; s < S_; s++) {
        int stg = s % 3;
        if (s < S_ - 1) CP_WAIT1(); else CP_WAIT0();
        __syncthreads();
        bool pf = (s + 2 < S_);
        if (pf) { ldgA((s + 2) * 32); loadB((s + 2) % 3, (s + 2) * 32); CP_COMMIT(); }

        uint32_t base = sb + stg * STG1;
        #pragma unroll
        for (int kk = 0; kk < 32; kk += 16) {
            uint32_t ah[4][4], al[4][4];
            #pragma unroll
            for (int mi = 0; mi < 4; mi++) {
                int row = wm + mi * 16 + (lane & 15);
                int col = kk + 8 * (lane >> 4);
                uint32_t off = (uint32_t)(row * P1 + col) * 2;
                LDSM4(ah[mi], base + off);
                LDSM4(al[mi], base + S1_AL + off);
            }
            #pragma unroll
            for (int hf = 0; hf < 2; hf++) {
                uint32_t bh[2][4], bl[2][4];
                #pragma unroll
                for (int nj = 0; nj < 2; nj++) {
                    int rown = hf * 128 + wn + nj * 16 + (lane & 7) + 8 * (lane >> 4);
                    int coln = kk + 8 * ((lane >> 3) & 1);
                    uint32_t off = (uint32_t)(rown * P1 + coln) * 2;
                    LDSM4(bh[nj], base + S1_BH + off);
                    LDSM4(bl[nj], base + S1_BL + off);
                }
                // term-major sweeps: 16 independent accumulators per sweep
                #pragma unroll
                for (int mi = 0; mi < 4; mi++)
                    #pragma unroll
                    for (int ni = 0; ni < 4; ni++)
                        mma16816(acc[hf][mi][ni], ah[mi],
                                 bh[ni >> 1][(ni & 1) * 2], bh[ni >> 1][(ni & 1) * 2 + 1]);
                #pragma unroll
                for (int mi = 0; mi < 4; mi++)
                    #pragma unroll
                    for (int ni = 0; ni < 4; ni++)
                        mma16816(acc[hf][mi][ni], ah[mi],
                                 bl[ni >> 1][(ni & 1) * 2], bl[ni >> 1][(ni & 1) * 2 + 1]);
                #pragma unroll
                for (int mi = 0; mi < 4; mi++)
                    #pragma unroll
                    for (int ni = 0; ni < 4; ni++)
                        mma16816(acc[hf][mi][ni], al[mi],
                                 bh[ni >> 1][(ni & 1) * 2], bh[ni >> 1][(ni & 1) * 2 + 1]);
            }
        }
        if (pf) stsA((s + 2) % 3);
    }

    // epilogue: bias + relu + split-store h hi/lo (full 256 cols)
    #pragma unroll
    for (int hf = 0; hf < 2; hf++)
        #pragma unroll
        for (int mi = 0; mi < 4; mi++) {
            #pragma unroll
            for (int h = 0; h < 2; h++) {
                int r = m0 + wm + mi * 16 + (lane >> 2) + 8 * h;
                if (r < M) {
                    #pragma unroll
                    for (int ni = 0; ni < 4; ni++) {
                        int col = hf * 128 + wn + ni * 8 + (lane & 3) * 2;
                        float v0 = fmaxf(acc[hf][mi][ni][2 * h + 0] + __ldg(bias1 + col), 0.f);
                        float v1 = fmaxf(acc[hf][mi][ni][2 * h + 1] + __ldg(bias1 + col + 1), 0.f);
                        uint32_t hi, lo;
                        splitpair(v0, v1, hi, lo);
                        *(uint32_t*)(g_h_hi + (size_t)r * 256 + col) = hi;
                        *(uint32_t*)(g_h_lo + (size_t)r * 256 + col) = lo;
                    }
                }
            }
        }
}

// ------- GEMM2: A-resident h tile; 2 n-blocks accumulator-resident per pass --
// 2 passes x 8 k-chunks. B double-buffered. Term-major MMA issue.
#define A2_PITCH 264
#define A2_BYTES (128 * A2_PITCH * 2)      // 67584 per array
#define B2_OFF   (2 * A2_BYTES)            // 135168
#define B2_BUF   40960                     // Bh(20480)+Bl(20480)
#define SMEM2    (B2_OFF + 2 * B2_BUF)     // 217088

__global__ __launch_bounds__(256, 1) void gemm2_kernel(
    const float* __restrict__ ba, const float* __restrict__ bb,
    const float* __restrict__ Wc, int M)
{
    extern __shared__ char dsm[];
    const uint32_t sb = smem_u32(dsm);
    __shared__ float sba[256], sbb[256], sWc[256], spart[512];
    const int t = threadIdx.x;
    const int lane = t & 31, w = t >> 5;
    const int m0 = blockIdx.x * 128;
    const int wm = (w >> 2) * 64, wn = (w & 3) * 32;

    sba[t] = ba[t]; sbb[t] = bb[t]; sWc[t] = Wc[t];

    auto loadB = [&](int buf, int u) {
        int pass = u >> 3, kc = u & 7;
        uint32_t dBh = sb + B2_OFF + buf * B2_BUF;
        uint32_t dBl = dBh + 20480;
        #pragma unroll
        for (int i = 0; i < 4; i++) {
            int id = t + 256 * i;
            int row = id >> 2, kcol = (id & 3) * 8;
            int nglob = (pass * 2 + (row >> 7)) * 128 + (row & 127);
            uint32_t doff = (uint32_t)(row * P1 + kcol) * 2;
            size_t so = (size_t)nglob * 256 + kc * 32 + kcol;
            cp16(dBh + doff, g_WabT_hi + so);
            cp16(dBl + doff, g_WabT_lo + so);
        }
    };

    // load full A tile (h hi/lo, 128 rows x 256 k) into resident SMEM
    #pragma unroll
    for (int i = 0; i < 16; i++) {
        int id = t + 256 * i;
        int row = id >> 5, ch = id & 31;
        uint32_t doff = (uint32_t)(row * A2_PITCH + ch * 8) * 2;
        size_t so = (size_t)(m0 + row) * 256 + ch * 8;
        cp16(sb + doff, g_h_hi + so);
        cp16(sb + A2_BYTES + doff, g_h_lo + so);
    }
    loadB(0, 0);
    CP_COMMIT(); CP_WAIT0();
    __syncthreads();

    float acc[2][4][4][4];
    float rp[4][2];
    #pragma unroll
    for (int mi = 0; mi < 4; mi++) { rp[mi][0] = 0.f; rp[mi][1] = 0.f; }

    for (int pass = 0; pass < 2; pass++) {
        #pragma unroll
        for (int nb = 0; nb < 2; nb++)
            #pragma unroll
            for (int mi = 0; mi < 4; mi++)
                #pragma unroll
                for (int ni = 0; ni < 4; ni++)
                    #pragma unroll
                    for (int q = 0; q < 4; q++) acc[nb][mi][ni][q] = 0.f;

        for (int kc = 0; kc < 8; kc++) {
            int u = pass * 8 + kc;
            int buf = u & 1;
            if (u + 1 < 16) { loadB(buf ^ 1, u + 1); CP_COMMIT(); }

            uint32_t baseB = sb + B2_OFF + buf * B2_BUF;
            #pragma unroll
            for (int kk = 0; kk < 32; kk += 16) {
                uint32_t ah[4][4], al[4][4];
                #pragma unroll
                for (int mi = 0; mi < 4; mi++) {
                    int row = wm + mi * 16 + (lane & 15);
                    int colg = kc * 32 + kk + 8 * (lane >> 4);
                    uint32_t off = (uint32_t)(row * A2_PITCH + colg) * 2;
                    LDSM4(ah[mi], sb + off);
                    LDSM4(al[mi], sb + A2_BYTES + off);
                }
                #pragma unroll
                for (int nb = 0; nb < 2; nb++) {
                    uint32_t bh[2][4], bl[2][4];
                    #pragma unroll
                    for (int nj = 0; nj < 2; nj++) {
                        int rown = nb * 128 + wn + nj * 16 + (lane & 7) + 8 * (lane >> 4);
                        int coln = kk + 8 * ((lane >> 3) & 1);
                        uint32_t off = (uint32_t)(rown * P1 + coln) * 2;
                        LDSM4(bh[nj], baseB + off);
                        LDSM4(bl[nj], baseB + 20480 + off);
                    }
                    // term-major sweeps: 16 independent accumulators per sweep
                    #pragma unroll
                    for (int mi = 0; mi < 4; mi++)
                        #pragma unroll
                        for (int ni = 0; ni < 4; ni++)
                            mma16816(acc[nb][mi][ni], ah[mi],
                                     bh[ni >> 1][(ni & 1) * 2], bh[ni >> 1][(ni & 1) * 2 + 1]);
                    #pragma unroll
                    for (int mi = 0; mi < 4; mi++)
                        #pragma unroll
                        for (int ni = 0; ni < 4; ni++)
                            mma16816(acc[nb][mi][ni], ah[mi],
                                     bl[ni >> 1][(ni & 1) * 2], bl[ni >> 1][(ni & 1) * 2 + 1]);
                    #pragma unroll
                    for (int mi = 0; mi < 4; mi++)
                        #pragma unroll
                        for (int ni = 0; ni < 4; ni++)
                            mma16816(acc[nb][mi][ni], al[mi],
                                     bh[ni >> 1][(ni & 1) * 2], bh[ni >> 1][(ni & 1) * 2 + 1]);
                }
            }
            if (kc == 7) {      // fold both n-blocks of this pass into raw partials
                #pragma unroll
                for (int nb = 0; nb < 2; nb++)
                    #pragma unroll
                    for (int mi = 0; mi < 4; mi++)
                        #pragma unroll
                        for (int ni = 0; ni < 4; ni++) {
                            int j = ((pass * 2 + nb) * 128 + wn + ni * 8 + (lane & 3) * 2) >> 1;
                            float bav = sba[j], bbv = sbb[j], wcv = sWc[j];
                            float av0 = acc[nb][mi][ni][0] + bav;
                            float bv0 = acc[nb][mi][ni][1] + bbv;
                            rp[mi][0] += tanhf(av0) * (1.f / (1.f + expf(-bv0))) * wcv;
                            float av1 = acc[nb][mi][ni][2] + bav;
                            float bv1 = acc[nb][mi][ni][3] + bbv;
                            rp[mi][1] += tanhf(av1) * (1.f / (1.f + expf(-bv1))) * wcv;
                        }
            }
            CP_WAIT0();
            __syncthreads();
        }
    }

    // reduce rp across quads then across the 4 n-warps
    #pragma unroll
    for (int mi = 0; mi < 4; mi++)
        #pragma unroll
        for (int h = 0; h < 2; h++) {
            rp[mi][h] += __shfl_xor_sync(0xffffffffu, rp[mi][h], 1);
            rp[mi][h] += __shfl_xor_sync(0xffffffffu, rp[mi][h], 2);
        }
    if ((lane & 3) == 0) {
        #pragma unroll
        for (int mi = 0; mi < 4; mi++)
            #pragma unroll
            for (int h = 0; h < 2; h++) {
                int rit = wm + mi * 16 + (lane >> 2) + 8 * h;
                spart[rit * 4 + (w & 3)] = rp[mi][h];
            }
    }
    __syncthreads();
    if (t < 128) {
        int r = m0 + t;
        if (r < M)
            d_raw[r] = spart[t * 4] + spart[t * 4 + 1] + spart[t * 4 + 2] + spart[t * 4 + 3];
    }
}

// ---------------- softmax partials over raw (deterministic two-stage) -------
__global__ __launch_bounds__(256) void stats1_kernel(int M)
{
    __shared__ float red[256];
    int t = threadIdx.x, b = blockIdx.x;
    int idx0 = b * 256 + t;
    float m = -INFINITY;
    for (int i = idx0; i < M; i += 65536) m = fmaxf(m, d_raw[i]);
    red[t] = m; __syncthreads();
    #pragma unroll
    for (int o = 128; o; o >>= 1) { if (t < o) red[t] = fmaxf(red[t], red[t + o]); __syncthreads(); }
    float bm = red[0];
    __syncthreads();
    float s = 0.f;
    for (int i = idx0; i < M; i += 65536) s += expf(d_raw[i] - bm);
    red[t] = s; __syncthreads();
    #pragma unroll
    for (int o = 128; o; o >>= 1) { if (t < o) red[t] += red[t + o]; __syncthreads(); }
    if (t == 0) { d_pm[b] = bm; d_ps[b] = red[0]; }
}

__global__ __launch_bounds__(256) void stats2_kernel()
{
    __shared__ float red[256];
    int t = threadIdx.x;
    float m = d_pm[t];
    red[t] = m; __syncthreads();
    #pragma unroll
    for (int o = 128; o; o >>= 1) { if (t < o) red[t] = fmaxf(red[t], red[t + o]); __syncthreads(); }
    float gmax = red[0];
    __syncthreads();
    float s = d_ps[t] * expf(m - gmax);
    red[t] = s; __syncthreads();
    #pragma unroll
    for (int o = 128; o; o >>= 1) { if (t < o) red[t] += red[t + o]; __syncthreads(); }
    if (t == 0) { d_stats[0] = gmax; d_stats[1] = red[0]; }
}

// ---------------- A = softmax(raw) -> out[0..M); partial gf = A@h ------------
__global__ __launch_bounds__(256) void afeat_kernel(float* __restrict__ out, int M)
{
    int t = threadIdx.x, b = blockIdx.x;
    int chunk = (M + 255) >> 8;
    int start = b * chunk;
    int end   = min(start + chunk, M);
    float gmax = d_stats[0];
    float inv  = 1.f / d_stats[1];
    float acc = 0.f;
    for (int r = start; r < end; r++) {
        float ar = expf(d_raw[r] - gmax) * inv;
        if ((r & 255) == t) out[r] = ar;
        size_t idx = (size_t)r * 256 + t;
        float hv = __bfloat162float(g_h_hi[idx]) + __bfloat162float(g_h_lo[idx]);
        acc = fmaf(ar, hv, acc);
    }
    d_pgf[b * 256 + t] = acc;
}

// ---------------- final: gf, hr = relu(gf@Wr+br), cls/reg heads --------------
__global__ __launch_bounds__(256) void head_kernel(
    const float* __restrict__ Wr,   const float* __restrict__ br,
    const float* __restrict__ Wcls, const float* __restrict__ bcls,
    const float* __restrict__ Wreg, const float* __restrict__ breg,
    float* __restrict__ out, int M)
{
    __shared__ float sgf[256], shr[256];
    int t = threadIdx.x;
    float acc = 0.f;
    #pragma unroll 8
    for (int b = 0; b < 256; b++) acc += d_pgf[b * 256 + t];
    sgf[t] = acc;
    out[M + t] = acc;
    __syncthreads();
    float v = br[t];
    #pragma unroll 8
    for (int k = 0; k < 256; k++) v = fmaf(sgf[k], Wr[k * 256 + t], v);
    shr[t] = fmaxf(v, 0.f);
    __syncthreads();
    if (t < 33) {
        float c = bcls[t];
        #pragma unroll 8
        for (int k = 0; k < 256; k++) c = fmaf(shr[k], Wcls[k * 33 + t], c);
        out[M + 256 + t] = c;
    } else if (t >= 64 && t < 119) {
        int j = t - 64;
        float c = breg[j];
        #pragma unroll 8
        for (int k = 0; k < 256; k++) c = fmaf(shr[k], Wreg[k * 55 + j], c);
        out[M + 289 + j] = c;
    }
}

// ---------------- launch ----------------
extern "C" void kernel_launch(void* const* d_in, const int* in_sizes, int n_in,
                              void* d_out, int out_size)
{
    const float* x    = (const float*)d_in[0];
    const float* W1   = (const float*)d_in[1];
    const float* b1   = (const float*)d_in[2];
    const float* Wa   = (const float*)d_in[3];
    const float* ba   = (const float*)d_in[4];
    const float* Wb   = (const float*)d_in[5];
    const float* bb   = (const float*)d_in[6];
    const float* Wc   = (const float*)d_in[7];
    // d_in[8] = bc : constant shift, cancels in softmax -> unused
    const float* Wr   = (const float*)d_in[9];
    const float* br   = (const float*)d_in[10];
    const float* Wcls = (const float*)d_in[11];
    const float* bcls = (const float*)d_in[12];
    const float* Wreg = (const float*)d_in[13];
    const float* breg = (const float*)d_in[14];
    float* out = (float*)d_out;
    int M = in_sizes[0] / 512;

    cudaFuncSetAttribute(gemm1_kernel, cudaFuncAttributeMaxDynamicSharedMemorySize, SMEM1);
    cudaFuncSetAttribute(gemm2_kernel, cudaFuncAttributeMaxDynamicSharedMemorySize, SMEM2);

    prep_w1 <<<512, 256>>>(W1);                                   // launch 1
    prep_wab<<<512, 256>>>(Wa, Wb);                               // launch 2
    gemm1_kernel<<<(M + 127) / 128, 256, SMEM1>>>(x, b1, M);      // launch 3
    gemm2_kernel<<<(M + 127) / 128, 256, SMEM2>>>(ba, bb, Wc, M); // launch 4 (profiled)
    stats1_kernel<<<256, 256>>>(M);
    stats2_kernel<<<1, 256>>>();
    afeat_kernel<<<256, 256>>>(out, M);
    head_kernel<<<1, 256>>>(Wr, br, Wcls, bcls, Wreg, breg, out, M);
}

// round 17
// speedup vs baseline: 1.2167x; 1.2126x over previous
#include <cuda_runtime.h>
#include <cuda_bf16.h>
#include <math.h>
#include <stdint.h>

#define MAXN 200704

// ---------------- scratch (static device globals; no runtime allocation) ----
__device__ __nv_bfloat16 g_h_hi[(size_t)MAXN * 256];
__device__ __nv_bfloat16 g_h_lo[(size_t)MAXN * 256];
__device__ __nv_bfloat16 g_W1T_hi[256 * 512];
__device__ __nv_bfloat16 g_W1T_lo[256 * 512];
__device__ __nv_bfloat16 g_WabT_hi[512 * 256];   // col-interleaved [Wa|Wb], [n][k]
__device__ __nv_bfloat16 g_WabT_lo[512 * 256];
__device__ float d_praw[(size_t)4 * MAXN];
__device__ float d_raw[MAXN];
__device__ float d_pm[256];
__device__ float d_ps[256];
__device__ float d_stats[2];
__device__ float d_pgf[512 * 256];

// ---------------- helpers ----------------
__device__ __forceinline__ uint32_t smem_u32(const void* p) {
    uint32_t a;
    asm("{ .reg .u64 t; cvta.to.shared.u64 t, %1; cvt.u32.u64 %0, t; }" : "=r"(a) : "l"(p));
    return a;
}
__device__ __forceinline__ void cp16(uint32_t dst, const void* src) {
    asm volatile("cp.async.cg.shared.global [%0], [%1], 16;" :: "r"(dst), "l"(src));
}
#define CP_COMMIT() asm volatile("cp.async.commit_group;" ::: "memory")
#define CP_WAIT0()  asm volatile("cp.async.wait_group 0;" ::: "memory")

#define LDSM4(r, addr) \
    asm volatile("ldmatrix.sync.aligned.m8n8.x4.shared.b16 {%0,%1,%2,%3}, [%4];" \
        : "=r"((r)[0]), "=r"((r)[1]), "=r"((r)[2]), "=r"((r)[3]) : "r"(addr))

__device__ __forceinline__ void mma16816(float* c, const uint32_t* a, uint32_t b0, uint32_t b1) {
    asm volatile("mma.sync.aligned.m16n8k16.row.col.f32.bf16.bf16.f32 "
        "{%0,%1,%2,%3}, {%4,%5,%6,%7}, {%8,%9}, {%0,%1,%2,%3};"
        : "+f"(c[0]), "+f"(c[1]), "+f"(c[2]), "+f"(c[3])
        : "r"(a[0]), "r"(a[1]), "r"(a[2]), "r"(a[3]), "r"(b0), "r"(b1));
}

__device__ __forceinline__ void splitpair(float v0, float v1, uint32_t& hi, uint32_t& lo) {
    __nv_bfloat162 h = __floats2bfloat162_rn(v0, v1);
    float l0 = v0 - __bfloat162float(h.x);
    float l1 = v1 - __bfloat162float(h.y);
    __nv_bfloat162 l = __floats2bfloat162_rn(l0, l1);
    hi = *reinterpret_cast<uint32_t*>(&h);
    lo = *reinterpret_cast<uint32_t*>(&l);
}

// ---------------- prep: transpose+split weights to bf16 hi/lo ----------------
__global__ __launch_bounds__(256) void prep_w1(const float* __restrict__ W1)
{
    int o = blockIdx.x * 256 + threadIdx.x;   // 512 blocks -> 131072
    int n = o >> 9, k = o & 511;
    float v = W1[k * 256 + n];
    __nv_bfloat16 h = __float2bfloat16(v);
    g_W1T_hi[o] = h;
    g_W1T_lo[o] = __float2bfloat16(v - __bfloat162float(h));
}
__global__ __launch_bounds__(256) void prep_wab(
    const float* __restrict__ Wa, const float* __restrict__ Wb)
{
    int o = blockIdx.x * 256 + threadIdx.x;   // 512 blocks -> 131072
    int n = o >> 8, k = o & 255;
    int j = n >> 1;
    float v = (n & 1) ? Wb[k * 256 + j] : Wa[k * 256 + j];
    __nv_bfloat16 h = __float2bfloat16(v);
    g_WabT_hi[o] = h;
    g_WabT_lo[o] = __float2bfloat16(v - __bfloat162float(h));
}

// ---------------- unified GEMM: 128 threads, tile 64m x 128n, BK=32 ----------
// MODE 0: h = relu(x@W1+b1), K=512, grid(2, M/64). A: LDG fp32 -> split -> STS.
// MODE 1: a/b logits -> fused raw partials, K=256, grid(4, M/64). A via cp.async.
// 2-stage cp.async, smem 60KB, 3 CTAs/SM -> barrier bubbles overlap across CTAs.
#define P1 40
#define SA_L  5120
#define SB_H  10240
#define SB_L  20480
#define STG   30720
#define SMEMG (2 * STG)

template<int MODE>
__global__ __launch_bounds__(128, 3) void gemm_mma(
    const float* __restrict__ Xf, const float* __restrict__ bias1,
    const float* __restrict__ ba, const float* __restrict__ bb,
    const float* __restrict__ Wc, int M)
{
    extern __shared__ char dsm[];
    const uint32_t sb = smem_u32(dsm);
    const int K = (MODE == 0) ? 512 : 256;
    const int S_ = K / 32;
    const __nv_bfloat16* __restrict__ BTh = (MODE == 0) ? g_W1T_hi : g_WabT_hi;
    const __nv_bfloat16* __restrict__ BTl = (MODE == 0) ? g_W1T_lo : g_WabT_lo;

    const int t = threadIdx.x;
    const int lane = t & 31, w = t >> 5;
    const int m0 = blockIdx.y * 64;
    const int n0 = blockIdx.x * 128;
    const int wn = w * 32;

    __shared__ float sba[256], sbb[256], sWc[256], spart[256];
    if (MODE == 1) {
        sba[t] = ba[t]; sba[t + 128] = ba[t + 128];
        sbb[t] = bb[t]; sbb[t + 128] = bb[t + 128];
        sWc[t] = Wc[t]; sWc[t + 128] = Wc[t + 128];
    }

    float areg[16];                  // MODE0 staging
    const int arow = t >> 1, akh = t & 1;

    auto loadB = [&](int stg, int kt) {
        uint32_t dBh = sb + stg * STG + SB_H;
        uint32_t dBl = sb + stg * STG + SB_L;
        #pragma unroll
        for (int i = 0; i < 4; i++) {
            int id = t + 128 * i;                // 0..511
            int row = id >> 2, kc = (id & 3) * 8;
            uint32_t doff = (uint32_t)(row * P1 + kc) * 2;
            size_t so = (size_t)(n0 + row) * K + kt + kc;
            cp16(dBh + doff, BTh + so);
            cp16(dBl + doff, BTl + so);
        }
    };
    auto loadA1 = [&](int stg, int kt) {         // MODE1: h hi/lo via cp.async
        uint32_t dAh = sb + stg * STG;
        uint32_t dAl = dAh + SA_L;
        #pragma unroll
        for (int i = 0; i < 2; i++) {
            int id = t + 128 * i;                // 0..255
            int row = id >> 2, kc = (id & 3) * 8;
            uint32_t doff = (uint32_t)(row * P1 + kc) * 2;
            size_t so = (size_t)(m0 + row) * 256 + kt + kc;
            cp16(dAh + doff, g_h_hi + so);
            cp16(dAl + doff, g_h_lo + so);
        }
    };
    auto ldgA = [&](int kt) {                    // MODE0: fp32 x
        const float* src = Xf + (size_t)(m0 + arow) * 512 + kt + akh * 16;
        bool ok = (m0 + arow) < M;
        #pragma unroll
        for (int q = 0; q < 4; q++) {
            float4 v = ok ? *(const float4*)(src + q * 4) : make_float4(0.f, 0.f, 0.f, 0.f);
            areg[q * 4 + 0] = v.x; areg[q * 4 + 1] = v.y;
            areg[q * 4 + 2] = v.z; areg[q * 4 + 3] = v.w;
        }
    };
    auto stsA = [&](int stg) {
        uint32_t hi[8], lo[8];
        #pragma unroll
        for (int p = 0; p < 8; p++) splitpair(areg[2 * p], areg[2 * p + 1], hi[p], lo[p]);
        char* bh = dsm + stg * STG + (arow * P1 + akh * 16) * 2;
        char* bl = bh + SA_L;
        *(uint4*)(bh)      = make_uint4(hi[0], hi[1], hi[2], hi[3]);
        *(uint4*)(bh + 16) = make_uint4(hi[4], hi[5], hi[6], hi[7]);
        *(uint4*)(bl)      = make_uint4(lo[0], lo[1], lo[2], lo[3]);
        *(uint4*)(bl + 16) = make_uint4(lo[4], lo[5], lo[6], lo[7]);
    };

    float acc[4][4][4];
    #pragma unroll
    for (int mi = 0; mi < 4; mi++)
        #pragma unroll
        for (int ni = 0; ni < 4; ni++)
            #pragma unroll
            for (int q = 0; q < 4; q++) acc[mi][ni][q] = 0.f;

    // prologue: stage 0 = chunk 0
    if (MODE == 0) { ldgA(0); stsA(0); } else { loadA1(0, 0); }
    loadB(0, 0);
    CP_COMMIT();

    for (int s = 0; s < S_; s++) {
        int stg = s & 1;
        CP_WAIT0();
        __syncthreads();
        bool pf = (s + 1 < S_);
        if (pf) {
            if (MODE == 0) ldgA((s + 1) * 32);
            else           loadA1(stg ^ 1, (s + 1) * 32);
            loadB(stg ^ 1, (s + 1) * 32);
            CP_COMMIT();
        }
        uint32_t base = sb + stg * STG;
        #pragma unroll
        for (int kk = 0; kk < 32; kk += 16) {
            uint32_t ah[4][4], al[4][4];
            #pragma unroll
            for (int mi = 0; mi < 4; mi++) {
                int row = mi * 16 + (lane & 15);
                int col = kk + 8 * (lane >> 4);
                uint32_t off = (uint32_t)(row * P1 + col) * 2;
                LDSM4(ah[mi], base + off);
                LDSM4(al[mi], base + SA_L + off);
            }
            uint32_t bh[2][4], bl[2][4];
            #pragma unroll
            for (int nj = 0; nj < 2; nj++) {
                int rown = wn + nj * 16 + (lane & 7) + 8 * (lane >> 4);
                int coln = kk + 8 * ((lane >> 3) & 1);
                uint32_t off = (uint32_t)(rown * P1 + coln) * 2;
                LDSM4(bh[nj], base + SB_H + off);
                LDSM4(bl[nj], base + SB_L + off);
            }
            #pragma unroll
            for (int mi = 0; mi < 4; mi++)
                #pragma unroll
                for (int ni = 0; ni < 4; ni++)
                    mma16816(acc[mi][ni], ah[mi],
                             bh[ni >> 1][(ni & 1) * 2], bh[ni >> 1][(ni & 1) * 2 + 1]);
            #pragma unroll
            for (int mi = 0; mi < 4; mi++)
                #pragma unroll
                for (int ni = 0; ni < 4; ni++)
                    mma16816(acc[mi][ni], ah[mi],
                             bl[ni >> 1][(ni & 1) * 2], bl[ni >> 1][(ni & 1) * 2 + 1]);
            #pragma unroll
            for (int mi = 0; mi < 4; mi++)
                #pragma unroll
                for (int ni = 0; ni < 4; ni++)
                    mma16816(acc[mi][ni], al[mi],
                             bh[ni >> 1][(ni & 1) * 2], bh[ni >> 1][(ni & 1) * 2 + 1]);
        }
        if (MODE == 0 && pf) stsA(stg ^ 1);
    }

    if (MODE == 0) {
        // epilogue: bias + relu + split-store h hi/lo
        #pragma unroll
        for (int mi = 0; mi < 4; mi++)
            #pragma unroll
            for (int h = 0; h < 2; h++) {
                int r = m0 + mi * 16 + (lane >> 2) + 8 * h;
                if (r < M) {
                    #pragma unroll
                    for (int ni = 0; ni < 4; ni++) {
                        int col = n0 + wn + ni * 8 + (lane & 3) * 2;
                        float v0 = fmaxf(acc[mi][ni][2 * h + 0] + __ldg(bias1 + col), 0.f);
                        float v1 = fmaxf(acc[mi][ni][2 * h + 1] + __ldg(bias1 + col + 1), 0.f);
                        uint32_t hi, lo;
                        splitpair(v0, v1, hi, lo);
                        *(uint32_t*)(g_h_hi + (size_t)r * 256 + col) = hi;
                        *(uint32_t*)(g_h_lo + (size_t)r * 256 + col) = lo;
                    }
                }
            }
    } else {
        // epilogue: raw partials = sum_j tanh(a+ba)*sigmoid(b+bb)*Wc over this CTA's 128 cols
        float rp[4][2];
        #pragma unroll
        for (int mi = 0; mi < 4; mi++) { rp[mi][0] = 0.f; rp[mi][1] = 0.f; }
        #pragma unroll
        for (int mi = 0; mi < 4; mi++)
            #pragma unroll
            for (int ni = 0; ni < 4; ni++) {
                int j = (n0 + wn + ni * 8 + (lane & 3) * 2) >> 1;
                float bav = sba[j], bbv = sbb[j], wcv = sWc[j];
                float av0 = acc[mi][ni][0] + bav;
                float bv0 = acc[mi][ni][1] + bbv;
                rp[mi][0] += tanhf(av0) * (1.f / (1.f + expf(-bv0))) * wcv;
                float av1 = acc[mi][ni][2] + bav;
                float bv1 = acc[mi][ni][3] + bbv;
                rp[mi][1] += tanhf(av1) * (1.f / (1.f + expf(-bv1))) * wcv;
            }
        #pragma unroll
        for (int mi = 0; mi < 4; mi++)
            #pragma unroll
            for (int h = 0; h < 2; h++) {
                rp[mi][h] += __shfl_xor_sync(0xffffffffu, rp[mi][h], 1);
                rp[mi][h] += __shfl_xor_sync(0xffffffffu, rp[mi][h], 2);
            }
        __syncthreads();
        if ((lane & 3) == 0) {
            #pragma unroll
            for (int mi = 0; mi < 4; mi++)
                #pragma unroll
                for (int h = 0; h < 2; h++) {
                    int rit = mi * 16 + (lane >> 2) + 8 * h;
                    spart[rit * 4 + w] = rp[mi][h];
                }
        }
        __syncthreads();
        if (t < 64) {
            int r = m0 + t;
            if (r < M)
                d_praw[(size_t)blockIdx.x * MAXN + r] =
                    spart[t * 4] + spart[t * 4 + 1] + spart[t * 4 + 2] + spart[t * 4 + 3];
        }
    }
}

// ---------------- softmax partials over raw (deterministic two-stage) -------
__global__ __launch_bounds__(256) void stats1_kernel(int M)
{
    __shared__ float red[256];
    int t = threadIdx.x, b = blockIdx.x;
    int idx0 = b * 256 + t;
    float m = -INFINITY;
    for (int i = idx0; i < M; i += 65536) {
        float r = d_praw[i] + d_praw[MAXN + i] + d_praw[2 * (size_t)MAXN + i]
                + d_praw[3 * (size_t)MAXN + i];
        d_raw[i] = r;
        m = fmaxf(m, r);
    }
    red[t] = m; __syncthreads();
    #pragma unroll
    for (int o = 128; o; o >>= 1) { if (t < o) red[t] = fmaxf(red[t], red[t + o]); __syncthreads(); }
    float bm = red[0];
    __syncthreads();
    float s = 0.f;
    for (int i = idx0; i < M; i += 65536) s += expf(d_raw[i] - bm);
    red[t] = s; __syncthreads();
    #pragma unroll
    for (int o = 128; o; o >>= 1) { if (t < o) red[t] += red[t + o]; __syncthreads(); }
    if (t == 0) { d_pm[b] = bm; d_ps[b] = red[0]; }
}

__global__ __launch_bounds__(256) void stats2_kernel()
{
    __shared__ float red[256];
    int t = threadIdx.x;
    float m = d_pm[t];
    red[t] = m; __syncthreads();
    #pragma unroll
    for (int o = 128; o; o >>= 1) { if (t < o) red[t] = fmaxf(red[t], red[t + o]); __syncthreads(); }
    float gmax = red[0];
    __syncthreads();
    float s = d_ps[t] * expf(m - gmax);
    red[t] = s; __syncthreads();
    #pragma unroll
    for (int o = 128; o; o >>= 1) { if (t < o) red[t] += red[t + o]; __syncthreads(); }
    if (t == 0) { d_stats[0] = gmax; d_stats[1] = red[0]; }
}

// ---------------- A = softmax(raw) -> out[0..M); partial gf = A@h ------------
__global__ __launch_bounds__(256) void afeat_kernel(float* __restrict__ out, int M)
{
    int t = threadIdx.x, b = blockIdx.x;
    int chunk = (M + 511) >> 9;
    int start = b * chunk;
    int end   = min(start + chunk, M);
    float gmax = d_stats[0];
    float inv  = 1.f / d_stats[1];
    float acc = 0.f;
    for (int r = start; r < end; r++) {
        float ar = expf(d_raw[r] - gmax) * inv;
        if ((r & 255) == t) out[r] = ar;
        size_t idx = (size_t)r * 256 + t;
        float hv = __bfloat162float(g_h_hi[idx]) + __bfloat162float(g_h_lo[idx]);
        acc = fmaf(ar, hv, acc);
    }
    d_pgf[b * 256 + t] = acc;
}

// ---------------- final: gf, hr = relu(gf@Wr+br), cls/reg heads --------------
__global__ __launch_bounds__(256) void head_kernel(
    const float* __restrict__ Wr,   const float* __restrict__ br,
    const float* __restrict__ Wcls, const float* __restrict__ bcls,
    const float* __restrict__ Wreg, const float* __restrict__ breg,
    float* __restrict__ out, int M)
{
    __shared__ float sgf[256], shr[256];
    int t = threadIdx.x;
    float acc = 0.f;
    #pragma unroll 8
    for (int b = 0; b < 512; b++) acc += d_pgf[b * 256 + t];
    sgf[t] = acc;
    out[M + t] = acc;
    __syncthreads();
    float v = br[t];
    #pragma unroll 8
    for (int k = 0; k < 256; k++) v = fmaf(sgf[k], Wr[k * 256 + t], v);
    shr[t] = fmaxf(v, 0.f);
    __syncthreads();
    if (t < 33) {
        float c = bcls[t];
        #pragma unroll 8
        for (int k = 0; k < 256; k++) c = fmaf(shr[k], Wcls[k * 33 + t], c);
        out[M + 256 + t] = c;
    } else if (t >= 64 && t < 119) {
        int j = t - 64;
        float c = breg[j];
        #pragma unroll 8
        for (int k = 0; k < 256; k++) c = fmaf(shr[k], Wreg[k * 55 + j], c);
        out[M + 289 + j] = c;
    }
}

// ---------------- launch ----------------
extern "C" void kernel_launch(void* const* d_in, const int* in_sizes, int n_in,
                              void* d_out, int out_size)
{
    const float* x    = (const float*)d_in[0];
    const float* W1   = (const float*)d_in[1];
    const float* b1   = (const float*)d_in[2];
    const float* Wa   = (const float*)d_in[3];
    const float* ba   = (const float*)d_in[4];
    const float* Wb   = (const float*)d_in[5];
    const float* bb   = (const float*)d_in[6];
    const float* Wc   = (const float*)d_in[7];
    // d_in[8] = bc : constant shift, cancels in softmax -> unused
    const float* Wr   = (const float*)d_in[9];
    const float* br   = (const float*)d_in[10];
    const float* Wcls = (const float*)d_in[11];
    const float* bcls = (const float*)d_in[12];
    const float* Wreg = (const float*)d_in[13];
    const float* breg = (const float*)d_in[14];
    float* out = (float*)d_out;
    int M = in_sizes[0] / 512;

    cudaFuncSetAttribute(gemm_mma<0>, cudaFuncAttributeMaxDynamicSharedMemorySize, SMEMG);
    cudaFuncSetAttribute(gemm_mma<1>, cudaFuncAttributeMaxDynamicSharedMemorySize, SMEMG);

    int mblk = (M + 63) / 64;
    prep_w1 <<<512, 256>>>(W1);                                            // launch 1
    prep_wab<<<512, 256>>>(Wa, Wb);                                        // launch 2
    gemm_mma<0><<<dim3(2, mblk), 128, SMEMG>>>(x, b1, b1, b1, b1, M);      // launch 3
    gemm_mma<1><<<dim3(4, mblk), 128, SMEMG>>>(nullptr, nullptr, ba, bb, Wc, M); // launch 4 (profiled)
    stats1_kernel<<<256, 256>>>(M);
    stats2_kernel<<<1, 256>>>();
    afeat_kernel<<<512, 256>>>(out, M);
    head_kernel<<<1, 256>>>(Wr, br, Wcls, bcls, Wreg, breg, out, M);
}